// round 12
// baseline (speedup 1.0000x reference)
#include <cuda_runtime.h>
#include <cuda_bf16.h>
#include <cstdint>
#include <cstring>

#define D      256
#define NSRC   4096
#define NTOT   8192
#define NBLK   64            // NTOT / 128
#define NPAIRS 2080          // NBLK*(NBLK+1)/2
#define NCOLB  512           // column-sum partial blocks (16 rows each)
#define EPSV   1e-6
#define KC     64            // K chunk (f32 columns per stage)

// ---- k_main dynamic smem layout ----
#define OFF_SQA    0         // 128 f32
#define OFF_SQB    512       // 128 f32
#define OFF_STAGE0 2048
#define MAT_SZ     16384     // 128 rows x 64 bf16 (128B rows, SW128)
#define STAGE_SZ   (4 * MAT_SZ)                  // A_hi, A_lo, B_hi, B_lo
#define SMEM_SZ    (OFF_STAGE0 + 2 * STAGE_SZ)   // 133120

// Scratch
__device__ float  g_sq[NTOT];
__device__ float  g_colpart[NCOLB * D];
__device__ float  g_c;                 // 1 / (16*bandwidth + eps)
__device__ double g_partials[NPAIRS];

// ========================= helpers =========================
__device__ __forceinline__ uint32_t smem_u32(const void* p) {
    uint32_t a;
    asm("{ .reg .u64 t; cvta.to.shared.u64 t, %1; cvt.u32.u64 %0, t; }"
        : "=r"(a) : "l"(p));
    return a;
}
#define SW128(off) ((off) ^ (((off) >> 3) & 0x70))

#define LDSM_X4(r, a)                                                        \
    asm volatile("ldmatrix.sync.aligned.m8n8.x4.shared.b16 {%0,%1,%2,%3}, [%4];" \
        : "=r"((r)[0]), "=r"((r)[1]), "=r"((r)[2]), "=r"((r)[3]) : "r"(a))

#define MMA_BF16(c, a, b0, b1)                                               \
    asm volatile("mma.sync.aligned.m16n8k16.row.col.f32.bf16.bf16.f32 "      \
        "{%0,%1,%2,%3}, {%4,%5,%6,%7}, {%8,%9}, {%0,%1,%2,%3};"              \
        : "+f"((c)[0]), "+f"((c)[1]), "+f"((c)[2]), "+f"((c)[3])             \
        : "r"((a)[0]), "r"((a)[1]), "r"((a)[2]), "r"((a)[3]),                \
          "r"(b0), "r"(b1))

__device__ __forceinline__ uint32_t b2u(__nv_bfloat162 h) {
    uint32_t u; memcpy(&u, &h, 4); return u;
}

// ---------------------------------------------------------------------------
// Pass 1a: per-row squared norms. One warp per row.
// ---------------------------------------------------------------------------
__global__ void k_sq(const float* __restrict__ src, const float* __restrict__ tgt) {
    int warp = (blockIdx.x * blockDim.x + threadIdx.x) >> 5;
    int lane = threadIdx.x & 31;
    if (warp >= NTOT) return;
    const float* row = (warp < NSRC) ? (src + (size_t)warp * D)
                                     : (tgt + (size_t)(warp - NSRC) * D);
    float s = 0.f;
#pragma unroll
    for (int j = 0; j < D / 32; j++) {
        float v = row[lane + 32 * j];
        s += v * v;
    }
#pragma unroll
    for (int o = 16; o; o >>= 1) s += __shfl_xor_sync(0xffffffffu, s, o);
    if (lane == 0) g_sq[warp] = s;
}

// ---------------------------------------------------------------------------
// Pass 1b: column-sum partials, 16 rows per block.
// ---------------------------------------------------------------------------
__global__ void k_col(const float* __restrict__ src, const float* __restrict__ tgt) {
    int b = blockIdx.x;
    int d = threadIdx.x;
    int g0 = b * 16;
    const float* base = (g0 < NSRC) ? (src + (size_t)g0 * D)
                                    : (tgt + (size_t)(g0 - NSRC) * D);
    float s = 0.f;
#pragma unroll
    for (int i = 0; i < 16; i++) s += base[(size_t)i * D + d];
    g_colpart[b * D + d] = s;
}

// ---------------------------------------------------------------------------
// Pass 1c: bandwidth via closed form: sum(L2) = 2*n*sum(sq) - 2*||colsum||^2
// 8 independent accumulators break the serial DADD chain.
// ---------------------------------------------------------------------------
__global__ void k_bw() {
    int d = threadIdx.x;
    double ca[8] = {0, 0, 0, 0, 0, 0, 0, 0};
#pragma unroll
    for (int b = 0; b < NCOLB; b += 8) {
#pragma unroll
        for (int j = 0; j < 8; j++) ca[j] += (double)g_colpart[(b + j) * D + d];
    }
    double cs = ((ca[0] + ca[1]) + (ca[2] + ca[3]))
              + ((ca[4] + ca[5]) + (ca[6] + ca[7]));
    double ssq_term = cs * cs;
    double s0 = 0.0, s1 = 0.0, s2 = 0.0, s3 = 0.0;
    for (int i = d; i < NTOT; i += 1024) {
        s0 += (double)g_sq[i];
        s1 += (double)g_sq[i + 256];
        s2 += (double)g_sq[i + 512];
        s3 += (double)g_sq[i + 768];
    }
    double sq_sum = (s0 + s1) + (s2 + s3);

    __shared__ double sh1[256], sh2[256];
    sh1[d] = ssq_term;
    sh2[d] = sq_sum;
    __syncthreads();
    for (int o = 128; o; o >>= 1) {
        if (d < o) { sh1[d] += sh1[d + o]; sh2[d] += sh2[d + o]; }
        __syncthreads();
    }
    if (d == 0) {
        double n     = (double)NTOT;
        double sumL2 = 2.0 * (n * sh2[0] - sh1[0]);
        double bw    = sumL2 / (n * n - n) / 4.0;
        g_c = (float)(1.0 / (bw * 16.0 + EPSV));
    }
}

// ---------------------------------------------------------------------------
// Pass 2: split-bf16 HMMA tile kernel, 512 threads (16 warps, 4x4 grid,
// warp tile 32x32) to double occupancy vs the 256-thread variant.
//   dot_f32(x,y) ~ hi.hi + hi.lo + lo.hi  (3 bf16 m16n8k16 MMAs per frag pair)
// All threads: LDG f32 -> bf16 hi/lo split -> SW128 STS ([idx][k] row-major).
// Double-buffered K chunks (KC=64) with register prefetch of the next chunk.
// Epilogue in registers; deterministic double reduction.
// ---------------------------------------------------------------------------
__global__ void __launch_bounds__(512, 1) k_main(const float* __restrict__ src,
                                                 const float* __restrict__ tgt) {
    extern __shared__ __align__(1024) char sm[];
    uint32_t sb = smem_u32(sm);

    // decode linear blockIdx -> (bi, bj) with bi <= bj
    int bi = 0, rem = blockIdx.x;
    while (rem >= NBLK - bi) { rem -= NBLK - bi; bi++; }
    int bj = bi + rem;

    const float* A = (bi < NBLK / 2) ? (src + (size_t)bi * 128 * D)
                                     : (tgt + (size_t)(bi - NBLK / 2) * 128 * D);
    const float* B = (bj < NBLK / 2) ? (src + (size_t)bj * 128 * D)
                                     : (tgt + (size_t)(bj - NBLK / 2) * 128 * D);

    int t    = threadIdx.x;
    int l    = t & 31;
    int wid  = t >> 5;
    int wm   = wid >> 2;          // 0..3 -> M offset wm*32
    int wn   = wid & 3;           // 0..3 -> N offset wn*32

    // sq caches
    float* sqa_sm = (float*)(sm + OFF_SQA);
    float* sqb_sm = (float*)(sm + OFF_SQB);
    if (t < 128)      sqa_sm[t] = g_sq[bi * 128 + t];
    else if (t < 256) sqb_sm[t - 128] = g_sq[bj * 128 + (t - 128)];

    float acc[2][4][4];
#pragma unroll
    for (int mi = 0; mi < 2; mi++)
#pragma unroll
        for (int ni = 0; ni < 4; ni++)
#pragma unroll
            for (int r = 0; r < 4; r++) acc[mi][ni][r] = 0.f;

    // per-thread load slots: 4 float4 per matrix per chunk (512 threads)
    int row4[4], q4[4];
#pragma unroll
    for (int p = 0; p < 4; p++) {
        int i = t + 512 * p;
        row4[p] = i >> 4;
        q4[p]   = i & 15;
    }

    float4 av[4], bv[4];
#pragma unroll
    for (int p = 0; p < 4; p++) {
        av[p] = *(const float4*)(A + (size_t)row4[p] * D + q4[p] * 4);
        bv[p] = *(const float4*)(B + (size_t)row4[p] * D + q4[p] * 4);
    }

    // ldmatrix lane address components (within a stage matrix)
    uint32_t a_lrow = (uint32_t)(l & 15);
    uint32_t a_lkb  = (uint32_t)((l >> 4) << 4);
    uint32_t b_ln   = (uint32_t)((l & 7) + ((l >> 4) << 3));
    uint32_t b_lkb  = (uint32_t)(((l >> 3) & 1) << 4);

    for (int c = 0; c < 4; c++) {
        int s = c & 1;
        char* stg = sm + OFF_STAGE0 + s * STAGE_SZ;

        // convert + store this chunk
#pragma unroll
        for (int p = 0; p < 4; p++) {
            uint32_t off = SW128((uint32_t)(row4[p] * 128 + q4[p] * 8));
            {
                float4 v = av[p];
                __nv_bfloat162 H01 = __floats2bfloat162_rn(v.x, v.y);
                __nv_bfloat162 H23 = __floats2bfloat162_rn(v.z, v.w);
                __nv_bfloat162 L01 = __floats2bfloat162_rn(
                    v.x - __low2float(H01), v.y - __high2float(H01));
                __nv_bfloat162 L23 = __floats2bfloat162_rn(
                    v.z - __low2float(H23), v.w - __high2float(H23));
                *(uint2*)(stg + off)          = make_uint2(b2u(H01), b2u(H23));
                *(uint2*)(stg + MAT_SZ + off) = make_uint2(b2u(L01), b2u(L23));
            }
            {
                float4 v = bv[p];
                __nv_bfloat162 H01 = __floats2bfloat162_rn(v.x, v.y);
                __nv_bfloat162 H23 = __floats2bfloat162_rn(v.z, v.w);
                __nv_bfloat162 L01 = __floats2bfloat162_rn(
                    v.x - __low2float(H01), v.y - __high2float(H01));
                __nv_bfloat162 L23 = __floats2bfloat162_rn(
                    v.z - __low2float(H23), v.w - __high2float(H23));
                *(uint2*)(stg + 2 * MAT_SZ + off) = make_uint2(b2u(H01), b2u(H23));
                *(uint2*)(stg + 3 * MAT_SZ + off) = make_uint2(b2u(L01), b2u(L23));
            }
        }

        // prefetch next chunk (overlaps with MMA below)
        if (c < 3) {
#pragma unroll
            for (int p = 0; p < 4; p++) {
                av[p] = *(const float4*)(A + (size_t)row4[p] * D + (c + 1) * KC + q4[p] * 4);
                bv[p] = *(const float4*)(B + (size_t)row4[p] * D + (c + 1) * KC + q4[p] * 4);
            }
        }
        __syncthreads();

        uint32_t ah_base = sb + OFF_STAGE0 + s * STAGE_SZ;
        uint32_t al_base = ah_base + MAT_SZ;
        uint32_t bh_base = ah_base + 2 * MAT_SZ;
        uint32_t bl_base = ah_base + 3 * MAT_SZ;

#pragma unroll
        for (int ks = 0; ks < 4; ks++) {
            uint32_t kb = (uint32_t)(ks * 32);
            uint32_t aH[2][4], aL[2][4], bH[2][4], bL[2][4];
#pragma unroll
            for (int mi = 0; mi < 2; mi++) {
                uint32_t rowb = (uint32_t)((wm * 32 + mi * 16) + a_lrow) * 128
                              + kb + a_lkb;
                uint32_t offA = SW128(rowb);
                LDSM_X4(aH[mi], ah_base + offA);
                LDSM_X4(aL[mi], al_base + offA);
            }
#pragma unroll
            for (int pr = 0; pr < 2; pr++) {
                uint32_t rowb = (uint32_t)((wn * 32 + pr * 16) + b_ln) * 128
                              + kb + b_lkb;
                uint32_t offB = SW128(rowb);
                LDSM_X4(bH[pr], bh_base + offB);
                LDSM_X4(bL[pr], bl_base + offB);
            }
#pragma unroll
            for (int mi = 0; mi < 2; mi++)
#pragma unroll
                for (int ni = 0; ni < 4; ni++) {
                    int pr = ni >> 1, hf = (ni & 1) * 2;
                    MMA_BF16(acc[mi][ni], aH[mi], bH[pr][hf], bH[pr][hf + 1]);
                    MMA_BF16(acc[mi][ni], aH[mi], bL[pr][hf], bL[pr][hf + 1]);
                    MMA_BF16(acc[mi][ni], aL[mi], bH[pr][hf], bH[pr][hf + 1]);
                }
        }
        __syncthreads();
    }

    // ------------- epilogue (registers -> exp chain -> reduce) -------------
    float cc  = g_c;
    int gid  = l >> 2;
    int tid4 = l & 3;
    double tsum = 0.0;
#pragma unroll
    for (int mi = 0; mi < 2; mi++) {
        int r0 = wm * 32 + mi * 16 + gid;
        float sa0 = sqa_sm[r0];
        float sa1 = sqa_sm[r0 + 8];
#pragma unroll
        for (int ni = 0; ni < 4; ni++) {
            int c0 = wn * 32 + ni * 8 + 2 * tid4;
            float sb0 = sqb_sm[c0];
            float sb1 = sqb_sm[c0 + 1];
            float L2a = sa0 + sb0 - 2.f * acc[mi][ni][0];
            float L2b = sa0 + sb1 - 2.f * acc[mi][ni][1];
            float L2c = sa1 + sb0 - 2.f * acc[mi][ni][2];
            float L2d = sa1 + sb1 - 2.f * acc[mi][ni][3];
            float ua = __expf(-L2a * cc), ub = __expf(-L2b * cc);
            float uc = __expf(-L2c * cc), ud = __expf(-L2d * cc);
            float ua2 = ua * ua, ua4 = ua2 * ua2, ua8 = ua4 * ua4;
            float ub2 = ub * ub, ub4 = ub2 * ub2, ub8 = ub4 * ub4;
            float uc2 = uc * uc, uc4 = uc2 * uc2, uc8 = uc4 * uc4;
            float ud2 = ud * ud, ud4 = ud2 * ud2, ud8 = ud4 * ud4;
            float s1 = (ua + ua2 + ua4 + ua8 + ua8 * ua8)
                     + (ub + ub2 + ub4 + ub8 + ub8 * ub8);
            float s2 = (uc + uc2 + uc4 + uc8 + uc8 * uc8)
                     + (ud + ud2 + ud4 + ud8 + ud8 * ud8);
            tsum += (double)(s1 + s2);
        }
    }

    __syncthreads();
    double* red = (double*)(sm + OFF_STAGE0);
    red[t] = tsum;
    __syncthreads();
    for (int o = 256; o; o >>= 1) {
        if (t < o) red[t] += red[t + o];
        __syncthreads();
    }
    if (t == 0) {
        double w   = (bi == bj) ? 1.0 : 2.0;
        double sgn = ((bi < NBLK / 2) == (bj < NBLK / 2)) ? 1.0 : -1.0;
        g_partials[blockIdx.x] = w * sgn * red[0];
    }
}

// ---------------------------------------------------------------------------
// Pass 3: deterministic final reduction -> scalar mean.
// ---------------------------------------------------------------------------
__global__ void k_final(float* __restrict__ out) {
    __shared__ double red[256];
    int t = threadIdx.x;
    double s = 0.0;
    for (int i = t; i < NPAIRS; i += 256) s += g_partials[i];
    red[t] = s;
    __syncthreads();
    for (int o = 128; o; o >>= 1) {
        if (t < o) red[t] += red[t + o];
        __syncthreads();
    }
    if (t == 0) out[0] = (float)(red[0] / ((double)NSRC * (double)NSRC));
}

// ---------------------------------------------------------------------------
extern "C" void kernel_launch(void* const* d_in, const int* in_sizes, int n_in,
                              void* d_out, int out_size) {
    const float* src = (const float*)d_in[0];
    const float* tgt = (const float*)d_in[1];
    (void)in_sizes; (void)n_in; (void)out_size;

    cudaFuncSetAttribute(k_main, cudaFuncAttributeMaxDynamicSharedMemorySize, SMEM_SZ);

    k_sq<<<NTOT / 8, 256>>>(src, tgt);
    k_col<<<NCOLB, 256>>>(src, tgt);
    k_bw<<<1, 256>>>();
    k_main<<<NPAIRS, 512, SMEM_SZ>>>(src, tgt);
    k_final<<<1, 256>>>((float*)d_out);
}

// round 16
// speedup vs baseline: 1.1283x; 1.1283x over previous
#include <cuda_runtime.h>
#include <cuda_bf16.h>
#include <cstdint>
#include <cstring>

#define D      256
#define NSRC   4096
#define NTOT   8192
#define NBLK   64            // NTOT / 128
#define NPAIRS 2080          // NBLK*(NBLK+1)/2
#define NCOLB  512           // column-sum partial blocks (16 rows each)
#define EPSV   1e-6
#define KC     64            // K chunk (f32 columns per stage)

// ---- k_main dynamic smem layout ----
#define OFF_SQA    0         // 128 f32
#define OFF_SQB    512       // 128 f32
#define OFF_STAGE0 2048
#define MAT_SZ     16384     // 128 rows x 64 bf16 (128B rows, SW128)
#define STAGE_SZ   (4 * MAT_SZ)                  // A_hi, A_lo, B_hi, B_lo
#define SMEM_SZ    (OFF_STAGE0 + 2 * STAGE_SZ)   // 133120

// Scratch
__device__ float  g_sq[NTOT];
__device__ float  g_colpart[NCOLB * D];
__device__ float  g_c;                 // 1 / (16*bandwidth + eps)
__device__ double g_partials[NPAIRS];
// Pre-swizzled bf16 hi/lo chunks: [block][kchunk][hi/lo][16KB]
__device__ __align__(16) char g_pre[NBLK][4][2][MAT_SZ];

// ========================= helpers =========================
__device__ __forceinline__ uint32_t smem_u32(const void* p) {
    uint32_t a;
    asm("{ .reg .u64 t; cvta.to.shared.u64 t, %1; cvt.u32.u64 %0, t; }"
        : "=r"(a) : "l"(p));
    return a;
}
#define SW128(off) ((off) ^ (((off) >> 3) & 0x70))

#define LDSM_X4(r, a)                                                        \
    asm volatile("ldmatrix.sync.aligned.m8n8.x4.shared.b16 {%0,%1,%2,%3}, [%4];" \
        : "=r"((r)[0]), "=r"((r)[1]), "=r"((r)[2]), "=r"((r)[3]) : "r"(a))

#define MMA_BF16(c, a, b0, b1)                                               \
    asm volatile("mma.sync.aligned.m16n8k16.row.col.f32.bf16.bf16.f32 "      \
        "{%0,%1,%2,%3}, {%4,%5,%6,%7}, {%8,%9}, {%0,%1,%2,%3};"              \
        : "+f"((c)[0]), "+f"((c)[1]), "+f"((c)[2]), "+f"((c)[3])             \
        : "r"((a)[0]), "r"((a)[1]), "r"((a)[2]), "r"((a)[3]),                \
          "r"(b0), "r"(b1))

#define CP_ASYNC16(dst, src)                                                 \
    asm volatile("cp.async.cg.shared.global [%0], [%1], 16;"                 \
                 :: "r"(dst), "l"(src) : "memory")
#define CP_COMMIT  asm volatile("cp.async.commit_group;" ::: "memory")
#define CP_WAIT1   asm volatile("cp.async.wait_group 1;" ::: "memory")
#define CP_WAIT0   asm volatile("cp.async.wait_group 0;" ::: "memory")

__device__ __forceinline__ uint32_t b2u(__nv_bfloat162 h) {
    uint32_t u; memcpy(&u, &h, 4); return u;
}

// ---------------------------------------------------------------------------
// Pass 0: one-time f32 -> bf16 hi/lo split, written PRE-SWIZZLED to global.
// Byte layout matches exactly what k_main's smem stages expect.
// Grid: 64 blocks x 4 chunks.
// ---------------------------------------------------------------------------
__global__ void k_convert(const float* __restrict__ src,
                          const float* __restrict__ tgt) {
    int b = blockIdx.x >> 2;
    int c = blockIdx.x & 3;
    const float* base = ((b < NBLK / 2) ? (src + (size_t)b * 128 * D)
                                        : (tgt + (size_t)(b - NBLK / 2) * 128 * D))
                        + c * KC;
    char* hi = g_pre[b][c][0];
    char* lo = g_pre[b][c][1];
    int t = threadIdx.x;
#pragma unroll
    for (int p = 0; p < 8; p++) {
        int i = t + 256 * p;
        int row = i >> 4, q = i & 15;
        float4 v = *(const float4*)(base + (size_t)row * D + q * 4);
        __nv_bfloat162 H01 = __floats2bfloat162_rn(v.x, v.y);
        __nv_bfloat162 H23 = __floats2bfloat162_rn(v.z, v.w);
        __nv_bfloat162 L01 = __floats2bfloat162_rn(
            v.x - __low2float(H01), v.y - __high2float(H01));
        __nv_bfloat162 L23 = __floats2bfloat162_rn(
            v.z - __low2float(H23), v.w - __high2float(H23));
        uint32_t off = SW128((uint32_t)(row * 128 + q * 8));
        *(uint2*)(hi + off) = make_uint2(b2u(H01), b2u(H23));
        *(uint2*)(lo + off) = make_uint2(b2u(L01), b2u(L23));
    }
}

// ---------------------------------------------------------------------------
// Pass 1a: per-row squared norms. One warp per row.
// ---------------------------------------------------------------------------
__global__ void k_sq(const float* __restrict__ src, const float* __restrict__ tgt) {
    int warp = (blockIdx.x * blockDim.x + threadIdx.x) >> 5;
    int lane = threadIdx.x & 31;
    if (warp >= NTOT) return;
    const float* row = (warp < NSRC) ? (src + (size_t)warp * D)
                                     : (tgt + (size_t)(warp - NSRC) * D);
    float s = 0.f;
#pragma unroll
    for (int j = 0; j < D / 32; j++) {
        float v = row[lane + 32 * j];
        s += v * v;
    }
#pragma unroll
    for (int o = 16; o; o >>= 1) s += __shfl_xor_sync(0xffffffffu, s, o);
    if (lane == 0) g_sq[warp] = s;
}

// ---------------------------------------------------------------------------
// Pass 1b: column-sum partials, 16 rows per block.
// ---------------------------------------------------------------------------
__global__ void k_col(const float* __restrict__ src, const float* __restrict__ tgt) {
    int b = blockIdx.x;
    int d = threadIdx.x;
    int g0 = b * 16;
    const float* base = (g0 < NSRC) ? (src + (size_t)g0 * D)
                                    : (tgt + (size_t)(g0 - NSRC) * D);
    float s = 0.f;
#pragma unroll
    for (int i = 0; i < 16; i++) s += base[(size_t)i * D + d];
    g_colpart[b * D + d] = s;
}

// ---------------------------------------------------------------------------
// Pass 1c: bandwidth via closed form: sum(L2) = 2*n*sum(sq) - 2*||colsum||^2
// ---------------------------------------------------------------------------
__global__ void k_bw() {
    int d = threadIdx.x;
    double ca[8] = {0, 0, 0, 0, 0, 0, 0, 0};
#pragma unroll
    for (int b = 0; b < NCOLB; b += 8) {
#pragma unroll
        for (int j = 0; j < 8; j++) ca[j] += (double)g_colpart[(b + j) * D + d];
    }
    double cs = ((ca[0] + ca[1]) + (ca[2] + ca[3]))
              + ((ca[4] + ca[5]) + (ca[6] + ca[7]));
    double ssq_term = cs * cs;
    double s0 = 0.0, s1 = 0.0, s2 = 0.0, s3 = 0.0;
    for (int i = d; i < NTOT; i += 1024) {
        s0 += (double)g_sq[i];
        s1 += (double)g_sq[i + 256];
        s2 += (double)g_sq[i + 512];
        s3 += (double)g_sq[i + 768];
    }
    double sq_sum = (s0 + s1) + (s2 + s3);

    __shared__ double sh1[256], sh2[256];
    sh1[d] = ssq_term;
    sh2[d] = sq_sum;
    __syncthreads();
    for (int o = 128; o; o >>= 1) {
        if (d < o) { sh1[d] += sh1[d + o]; sh2[d] += sh2[d + o]; }
        __syncthreads();
    }
    if (d == 0) {
        double n     = (double)NTOT;
        double sumL2 = 2.0 * (n * sh2[0] - sh1[0]);
        double bw    = sumL2 / (n * n - n) / 4.0;
        g_c = (float)(1.0 / (bw * 16.0 + EPSV));
    }
}

// ---------------------------------------------------------------------------
// cp.async feed: copy 4 pre-swizzled 16KB matrices into a stage.
// ---------------------------------------------------------------------------
__device__ __forceinline__ void issue_chunk(uint32_t stage_sb, int bi, int bj,
                                            int c, int t) {
    const char* s0 = g_pre[bi][c][0] + t * 16;
    const char* s1 = g_pre[bi][c][1] + t * 16;
    const char* s2 = g_pre[bj][c][0] + t * 16;
    const char* s3 = g_pre[bj][c][1] + t * 16;
    uint32_t d0 = stage_sb + t * 16;
#pragma unroll
    for (int r = 0; r < 4; r++) CP_ASYNC16(d0 + r * 4096, s0 + r * 4096);
#pragma unroll
    for (int r = 0; r < 4; r++) CP_ASYNC16(d0 + MAT_SZ + r * 4096, s1 + r * 4096);
#pragma unroll
    for (int r = 0; r < 4; r++) CP_ASYNC16(d0 + 2 * MAT_SZ + r * 4096, s2 + r * 4096);
#pragma unroll
    for (int r = 0; r < 4; r++) CP_ASYNC16(d0 + 3 * MAT_SZ + r * 4096, s3 + r * 4096);
}

// ---------------------------------------------------------------------------
// Pass 2: split-bf16 HMMA tile kernel fed by cp.async from pre-converted
// buffers. 256 threads, 8 warps 4(M)x2(N), warp tile 32x64.
//   dot_f32(x,y) ~ hi.hi + hi.lo + lo.hi  (pass-major: 16 independent MMAs
//   between accumulator reuses -> no RAW chains)
// Double-buffered stages; chunk c+1 copies overlap chunk c MMAs.
// ---------------------------------------------------------------------------
__global__ void __launch_bounds__(256, 1) k_main(const float* __restrict__ src,
                                                 const float* __restrict__ tgt) {
    extern __shared__ __align__(1024) char sm[];
    uint32_t sb = smem_u32(sm);

    // decode linear blockIdx -> (bi, bj) with bi <= bj
    int bi = 0, rem = blockIdx.x;
    while (rem >= NBLK - bi) { rem -= NBLK - bi; bi++; }
    int bj = bi + rem;

    int t    = threadIdx.x;
    int l    = t & 31;
    int wid  = t >> 5;
    int wm   = wid >> 1;          // 0..3 -> M offset wm*32
    int wn   = wid & 1;           // 0..1 -> N offset wn*64

    // kick off chunk 0 immediately
    issue_chunk(sb + OFF_STAGE0, bi, bj, 0, t);
    CP_COMMIT;

    // sq caches
    float* sqa_sm = (float*)(sm + OFF_SQA);
    float* sqb_sm = (float*)(sm + OFF_SQB);
    if (t < 128) sqa_sm[t] = g_sq[bi * 128 + t];
    else         sqb_sm[t - 128] = g_sq[bj * 128 + (t - 128)];

    float acc[2][8][4];
#pragma unroll
    for (int mi = 0; mi < 2; mi++)
#pragma unroll
        for (int ni = 0; ni < 8; ni++)
#pragma unroll
            for (int r = 0; r < 4; r++) acc[mi][ni][r] = 0.f;

    // ldmatrix lane address components (within a stage matrix)
    uint32_t a_lrow = (uint32_t)(l & 15);
    uint32_t a_lkb  = (uint32_t)((l >> 4) << 4);
    uint32_t b_ln   = (uint32_t)((l & 7) + ((l >> 4) << 3));
    uint32_t b_lkb  = (uint32_t)(((l >> 3) & 1) << 4);

    for (int c = 0; c < 4; c++) {
        int s = c & 1;
        if (c < 3) {
            issue_chunk(sb + OFF_STAGE0 + ((c + 1) & 1) * STAGE_SZ, bi, bj, c + 1, t);
            CP_COMMIT;
            CP_WAIT1;          // chunk c complete, c+1 in flight
        } else {
            CP_WAIT0;
        }
        __syncthreads();

        uint32_t ah_base = sb + OFF_STAGE0 + s * STAGE_SZ;
        uint32_t al_base = ah_base + MAT_SZ;
        uint32_t bh_base = ah_base + 2 * MAT_SZ;
        uint32_t bl_base = ah_base + 3 * MAT_SZ;

#pragma unroll
        for (int ks = 0; ks < 4; ks++) {
            uint32_t kb = (uint32_t)(ks * 32);
            uint32_t aH[2][4], aL[2][4], bH[4][4], bL[4][4];
#pragma unroll
            for (int mi = 0; mi < 2; mi++) {
                uint32_t rowb = (uint32_t)((wm * 32 + mi * 16) + a_lrow) * 128
                              + kb + a_lkb;
                uint32_t offA = SW128(rowb);
                LDSM_X4(aH[mi], ah_base + offA);
                LDSM_X4(aL[mi], al_base + offA);
            }
#pragma unroll
            for (int pr = 0; pr < 4; pr++) {
                uint32_t rowb = (uint32_t)((wn * 64 + pr * 16) + b_ln) * 128
                              + kb + b_lkb;
                uint32_t offB = SW128(rowb);
                LDSM_X4(bH[pr], bh_base + offB);
                LDSM_X4(bL[pr], bl_base + offB);
            }
            // pass-major: 16 independent MMAs per pass -> no RAW chains
#pragma unroll
            for (int mi = 0; mi < 2; mi++)
#pragma unroll
                for (int ni = 0; ni < 8; ni++) {
                    int pr = ni >> 1, hf = (ni & 1) * 2;
                    MMA_BF16(acc[mi][ni], aH[mi], bH[pr][hf], bH[pr][hf + 1]);
                }
#pragma unroll
            for (int mi = 0; mi < 2; mi++)
#pragma unroll
                for (int ni = 0; ni < 8; ni++) {
                    int pr = ni >> 1, hf = (ni & 1) * 2;
                    MMA_BF16(acc[mi][ni], aH[mi], bL[pr][hf], bL[pr][hf + 1]);
                }
#pragma unroll
            for (int mi = 0; mi < 2; mi++)
#pragma unroll
                for (int ni = 0; ni < 8; ni++) {
                    int pr = ni >> 1, hf = (ni & 1) * 2;
                    MMA_BF16(acc[mi][ni], aL[mi], bH[pr][hf], bH[pr][hf + 1]);
                }
        }
        __syncthreads();
    }

    // ------------- epilogue (registers -> exp chain -> reduce) -------------
    float cc  = g_c;
    int gid  = l >> 2;
    int tid4 = l & 3;
    double tsum = 0.0;
#pragma unroll
    for (int mi = 0; mi < 2; mi++) {
        int r0 = wm * 32 + mi * 16 + gid;
        float sa0 = sqa_sm[r0];
        float sa1 = sqa_sm[r0 + 8];
#pragma unroll
        for (int ni = 0; ni < 8; ni++) {
            int c0 = wn * 64 + ni * 8 + 2 * tid4;
            float sb0 = sqb_sm[c0];
            float sb1 = sqb_sm[c0 + 1];
            float L2a = sa0 + sb0 - 2.f * acc[mi][ni][0];
            float L2b = sa0 + sb1 - 2.f * acc[mi][ni][1];
            float L2c = sa1 + sb0 - 2.f * acc[mi][ni][2];
            float L2d = sa1 + sb1 - 2.f * acc[mi][ni][3];
            float ua = __expf(-L2a * cc), ub = __expf(-L2b * cc);
            float uc = __expf(-L2c * cc), ud = __expf(-L2d * cc);
            float ua2 = ua * ua, ua4 = ua2 * ua2, ua8 = ua4 * ua4;
            float ub2 = ub * ub, ub4 = ub2 * ub2, ub8 = ub4 * ub4;
            float uc2 = uc * uc, uc4 = uc2 * uc2, uc8 = uc4 * uc4;
            float ud2 = ud * ud, ud4 = ud2 * ud2, ud8 = ud4 * ud4;
            float s1 = (ua + ua2 + ua4 + ua8 + ua8 * ua8)
                     + (ub + ub2 + ub4 + ub8 + ub8 * ub8);
            float s2 = (uc + uc2 + uc4 + uc8 + uc8 * uc8)
                     + (ud + ud2 + ud4 + ud8 + ud8 * ud8);
            tsum += (double)(s1 + s2);
        }
    }

    __syncthreads();
    double* red = (double*)(sm + OFF_STAGE0);
    red[t] = tsum;
    __syncthreads();
    for (int o = 128; o; o >>= 1) {
        if (t < o) red[t] += red[t + o];
        __syncthreads();
    }
    if (t == 0) {
        double w   = (bi == bj) ? 1.0 : 2.0;
        double sgn = ((bi < NBLK / 2) == (bj < NBLK / 2)) ? 1.0 : -1.0;
        g_partials[blockIdx.x] = w * sgn * red[0];
    }
}

// ---------------------------------------------------------------------------
// Pass 3: deterministic final reduction -> scalar mean.
// ---------------------------------------------------------------------------
__global__ void k_final(float* __restrict__ out) {
    __shared__ double red[256];
    int t = threadIdx.x;
    double s = 0.0;
    for (int i = t; i < NPAIRS; i += 256) s += g_partials[i];
    red[t] = s;
    __syncthreads();
    for (int o = 128; o; o >>= 1) {
        if (t < o) red[t] += red[t + o];
        __syncthreads();
    }
    if (t == 0) out[0] = (float)(red[0] / ((double)NSRC * (double)NSRC));
}

// ---------------------------------------------------------------------------
extern "C" void kernel_launch(void* const* d_in, const int* in_sizes, int n_in,
                              void* d_out, int out_size) {
    const float* src = (const float*)d_in[0];
    const float* tgt = (const float*)d_in[1];
    (void)in_sizes; (void)n_in; (void)out_size;

    cudaFuncSetAttribute(k_main, cudaFuncAttributeMaxDynamicSharedMemorySize, SMEM_SZ);

    k_convert<<<NBLK * 4, 256>>>(src, tgt);
    k_sq<<<NTOT / 8, 256>>>(src, tgt);
    k_col<<<NCOLB, 256>>>(src, tgt);
    k_bw<<<1, 256>>>();
    k_main<<<NPAIRS, 256, SMEM_SZ>>>(src, tgt);
    k_final<<<1, 256>>>((float*)d_out);
}

// round 17
// speedup vs baseline: 1.4956x; 1.3255x over previous
#include <cuda_runtime.h>
#include <cuda_bf16.h>
#include <cstdint>
#include <cstring>

#define D      256
#define NSRC   4096
#define NTOT   8192
#define NBLK   64            // NTOT / 128
#define NPAIRS 2080          // NBLK*(NBLK+1)/2
#define NCOLB  512           // column-sum partial blocks (16 rows each)
#define EPSV   1e-6
#define KC     64            // K chunk (f32 columns per stage)

// ---- k_main dynamic smem layout ----
#define OFF_SQA    0         // 128 f32
#define OFF_SQB    512       // 128 f32
#define OFF_STAGE0 2048
#define MAT_SZ     16384     // 128 rows x 64 bf16 (128B rows, SW128)
#define STAGE_SZ   (4 * MAT_SZ)                  // A_hi, A_lo, B_hi, B_lo
#define SMEM_SZ    (OFF_STAGE0 + 2 * STAGE_SZ)   // 133120

// Scratch
__device__ float  g_sq[NTOT];
__device__ float  g_colpart[NCOLB * D];
__device__ double g_colsum[D];
__device__ float  g_c;                 // 1 / (16*bandwidth + eps)
__device__ double g_partials[NPAIRS];
// Pre-swizzled bf16 hi/lo chunks: [block][kchunk][hi/lo][16KB]
__device__ __align__(16) char g_pre[NBLK][4][2][MAT_SZ];

// ========================= helpers =========================
__device__ __forceinline__ uint32_t smem_u32(const void* p) {
    uint32_t a;
    asm("{ .reg .u64 t; cvta.to.shared.u64 t, %1; cvt.u32.u64 %0, t; }"
        : "=r"(a) : "l"(p));
    return a;
}
#define SW128(off) ((off) ^ (((off) >> 3) & 0x70))

#define LDSM_X4(r, a)                                                        \
    asm volatile("ldmatrix.sync.aligned.m8n8.x4.shared.b16 {%0,%1,%2,%3}, [%4];" \
        : "=r"((r)[0]), "=r"((r)[1]), "=r"((r)[2]), "=r"((r)[3]) : "r"(a))

#define MMA_BF16(c, a, b0, b1)                                               \
    asm volatile("mma.sync.aligned.m16n8k16.row.col.f32.bf16.bf16.f32 "      \
        "{%0,%1,%2,%3}, {%4,%5,%6,%7}, {%8,%9}, {%0,%1,%2,%3};"              \
        : "+f"((c)[0]), "+f"((c)[1]), "+f"((c)[2]), "+f"((c)[3])             \
        : "r"((a)[0]), "r"((a)[1]), "r"((a)[2]), "r"((a)[3]),                \
          "r"(b0), "r"(b1))

#define CP_ASYNC16(dst, src)                                                 \
    asm volatile("cp.async.cg.shared.global [%0], [%1], 16;"                 \
                 :: "r"(dst), "l"(src) : "memory")
#define CP_COMMIT  asm volatile("cp.async.commit_group;" ::: "memory")
#define CP_WAIT1   asm volatile("cp.async.wait_group 1;" ::: "memory")
#define CP_WAIT0   asm volatile("cp.async.wait_group 0;" ::: "memory")

__device__ __forceinline__ uint32_t b2u(__nv_bfloat162 h) {
    uint32_t u; memcpy(&u, &h, 4); return u;
}

// ---------------------------------------------------------------------------
// Pass 0: one-time f32 -> bf16 hi/lo split, written PRE-SWIZZLED to global.
// Byte layout matches exactly what k_main's smem stages expect.
// Grid: 64 blocks x 4 chunks.
// ---------------------------------------------------------------------------
__global__ void k_convert(const float* __restrict__ src,
                          const float* __restrict__ tgt) {
    int b = blockIdx.x >> 2;
    int c = blockIdx.x & 3;
    const float* base = ((b < NBLK / 2) ? (src + (size_t)b * 128 * D)
                                        : (tgt + (size_t)(b - NBLK / 2) * 128 * D))
                        + c * KC;
    char* hi = g_pre[b][c][0];
    char* lo = g_pre[b][c][1];
    int t = threadIdx.x;
#pragma unroll
    for (int p = 0; p < 8; p++) {
        int i = t + 256 * p;
        int row = i >> 4, q = i & 15;
        float4 v = *(const float4*)(base + (size_t)row * D + q * 4);
        __nv_bfloat162 H01 = __floats2bfloat162_rn(v.x, v.y);
        __nv_bfloat162 H23 = __floats2bfloat162_rn(v.z, v.w);
        __nv_bfloat162 L01 = __floats2bfloat162_rn(
            v.x - __low2float(H01), v.y - __high2float(H01));
        __nv_bfloat162 L23 = __floats2bfloat162_rn(
            v.z - __low2float(H23), v.w - __high2float(H23));
        uint32_t off = SW128((uint32_t)(row * 128 + q * 8));
        *(uint2*)(hi + off) = make_uint2(b2u(H01), b2u(H23));
        *(uint2*)(lo + off) = make_uint2(b2u(L01), b2u(L23));
    }
}

// ---------------------------------------------------------------------------
// Pass 1a: per-row squared norms. One warp per row.
// ---------------------------------------------------------------------------
__global__ void k_sq(const float* __restrict__ src, const float* __restrict__ tgt) {
    int warp = (blockIdx.x * blockDim.x + threadIdx.x) >> 5;
    int lane = threadIdx.x & 31;
    if (warp >= NTOT) return;
    const float* row = (warp < NSRC) ? (src + (size_t)warp * D)
                                     : (tgt + (size_t)(warp - NSRC) * D);
    float s = 0.f;
#pragma unroll
    for (int j = 0; j < D / 32; j++) {
        float v = row[lane + 32 * j];
        s += v * v;
    }
#pragma unroll
    for (int o = 16; o; o >>= 1) s += __shfl_xor_sync(0xffffffffu, s, o);
    if (lane == 0) g_sq[warp] = s;
}

// ---------------------------------------------------------------------------
// Pass 1b: column-sum partials, 16 rows per block.
// ---------------------------------------------------------------------------
__global__ void k_col(const float* __restrict__ src, const float* __restrict__ tgt) {
    int b = blockIdx.x;
    int d = threadIdx.x;
    int g0 = b * 16;
    const float* base = (g0 < NSRC) ? (src + (size_t)g0 * D)
                                    : (tgt + (size_t)(g0 - NSRC) * D);
    float s = 0.f;
#pragma unroll
    for (int i = 0; i < 16; i++) s += base[(size_t)i * D + d];
    g_colpart[b * D + d] = s;
}

// ---------------------------------------------------------------------------
// Pass 1c (stage 1): fold 512 column partials -> g_colsum[d].
// One block per dimension d; all SMs busy; L2-resident reads; deterministic
// shared-memory tree.
// ---------------------------------------------------------------------------
__global__ void k_colsum() {
    int d = blockIdx.x;
    int t = threadIdx.x;
    __shared__ double sh[256];
    sh[t] = (double)g_colpart[(size_t)t * D + d]
          + (double)g_colpart[(size_t)(t + 256) * D + d];
    __syncthreads();
    for (int o = 128; o; o >>= 1) {
        if (t < o) sh[t] += sh[t + o];
        __syncthreads();
    }
    if (t == 0) g_colsum[d] = sh[0];
}

// ---------------------------------------------------------------------------
// Pass 1c (stage 2): bandwidth via closed form:
//   sum(L2) = 2*n*sum(sq) - 2*||colsum||^2
// Tiny single block; all heavy reduction already done in k_colsum.
// ---------------------------------------------------------------------------
__global__ void k_bwf() {
    int d = threadIdx.x;
    double cs = g_colsum[d];
    double ssq_term = cs * cs;
    double s0 = 0.0, s1 = 0.0, s2 = 0.0, s3 = 0.0;
    for (int i = d; i < NTOT; i += 1024) {
        s0 += (double)g_sq[i];
        s1 += (double)g_sq[i + 256];
        s2 += (double)g_sq[i + 512];
        s3 += (double)g_sq[i + 768];
    }
    double sq_sum = (s0 + s1) + (s2 + s3);

    __shared__ double sh1[256], sh2[256];
    sh1[d] = ssq_term;
    sh2[d] = sq_sum;
    __syncthreads();
    for (int o = 128; o; o >>= 1) {
        if (d < o) { sh1[d] += sh1[d + o]; sh2[d] += sh2[d + o]; }
        __syncthreads();
    }
    if (d == 0) {
        double n     = (double)NTOT;
        double sumL2 = 2.0 * (n * sh2[0] - sh1[0]);
        double bw    = sumL2 / (n * n - n) / 4.0;
        g_c = (float)(1.0 / (bw * 16.0 + EPSV));
    }
}

// ---------------------------------------------------------------------------
// cp.async feed: copy 4 pre-swizzled 16KB matrices into a stage.
// ---------------------------------------------------------------------------
__device__ __forceinline__ void issue_chunk(uint32_t stage_sb, int bi, int bj,
                                            int c, int t) {
    const char* s0 = g_pre[bi][c][0] + t * 16;
    const char* s1 = g_pre[bi][c][1] + t * 16;
    const char* s2 = g_pre[bj][c][0] + t * 16;
    const char* s3 = g_pre[bj][c][1] + t * 16;
    uint32_t d0 = stage_sb + t * 16;
#pragma unroll
    for (int r = 0; r < 4; r++) CP_ASYNC16(d0 + r * 4096, s0 + r * 4096);
#pragma unroll
    for (int r = 0; r < 4; r++) CP_ASYNC16(d0 + MAT_SZ + r * 4096, s1 + r * 4096);
#pragma unroll
    for (int r = 0; r < 4; r++) CP_ASYNC16(d0 + 2 * MAT_SZ + r * 4096, s2 + r * 4096);
#pragma unroll
    for (int r = 0; r < 4; r++) CP_ASYNC16(d0 + 3 * MAT_SZ + r * 4096, s3 + r * 4096);
}

// ---------------------------------------------------------------------------
// Pass 2: split-bf16 HMMA tile kernel fed by cp.async from pre-converted
// buffers. 256 threads, 8 warps 4(M)x2(N), warp tile 32x64.
//   dot_f32(x,y) ~ hi.hi + hi.lo + lo.hi  (pass-major: 16 independent MMAs
//   between accumulator reuses -> no RAW chains)
// Double-buffered stages; chunk c+1 copies overlap chunk c MMAs.
// ---------------------------------------------------------------------------
__global__ void __launch_bounds__(256, 1) k_main(const float* __restrict__ src,
                                                 const float* __restrict__ tgt) {
    extern __shared__ __align__(1024) char sm[];
    uint32_t sb = smem_u32(sm);

    // decode linear blockIdx -> (bi, bj) with bi <= bj
    int bi = 0, rem = blockIdx.x;
    while (rem >= NBLK - bi) { rem -= NBLK - bi; bi++; }
    int bj = bi + rem;

    int t    = threadIdx.x;
    int l    = t & 31;
    int wid  = t >> 5;
    int wm   = wid >> 1;          // 0..3 -> M offset wm*32
    int wn   = wid & 1;           // 0..1 -> N offset wn*64

    // kick off chunk 0 immediately
    issue_chunk(sb + OFF_STAGE0, bi, bj, 0, t);
    CP_COMMIT;

    // sq caches
    float* sqa_sm = (float*)(sm + OFF_SQA);
    float* sqb_sm = (float*)(sm + OFF_SQB);
    if (t < 128) sqa_sm[t] = g_sq[bi * 128 + t];
    else         sqb_sm[t - 128] = g_sq[bj * 128 + (t - 128)];

    float acc[2][8][4];
#pragma unroll
    for (int mi = 0; mi < 2; mi++)
#pragma unroll
        for (int ni = 0; ni < 8; ni++)
#pragma unroll
            for (int r = 0; r < 4; r++) acc[mi][ni][r] = 0.f;

    // ldmatrix lane address components (within a stage matrix)
    uint32_t a_lrow = (uint32_t)(l & 15);
    uint32_t a_lkb  = (uint32_t)((l >> 4) << 4);
    uint32_t b_ln   = (uint32_t)((l & 7) + ((l >> 4) << 3));
    uint32_t b_lkb  = (uint32_t)(((l >> 3) & 1) << 4);

    for (int c = 0; c < 4; c++) {
        int s = c & 1;
        if (c < 3) {
            issue_chunk(sb + OFF_STAGE0 + ((c + 1) & 1) * STAGE_SZ, bi, bj, c + 1, t);
            CP_COMMIT;
            CP_WAIT1;          // chunk c complete, c+1 in flight
        } else {
            CP_WAIT0;
        }
        __syncthreads();

        uint32_t ah_base = sb + OFF_STAGE0 + s * STAGE_SZ;
        uint32_t al_base = ah_base + MAT_SZ;
        uint32_t bh_base = ah_base + 2 * MAT_SZ;
        uint32_t bl_base = ah_base + 3 * MAT_SZ;

#pragma unroll
        for (int ks = 0; ks < 4; ks++) {
            uint32_t kb = (uint32_t)(ks * 32);
            uint32_t aH[2][4], aL[2][4], bH[4][4], bL[4][4];
#pragma unroll
            for (int mi = 0; mi < 2; mi++) {
                uint32_t rowb = (uint32_t)((wm * 32 + mi * 16) + a_lrow) * 128
                              + kb + a_lkb;
                uint32_t offA = SW128(rowb);
                LDSM_X4(aH[mi], ah_base + offA);
                LDSM_X4(aL[mi], al_base + offA);
            }
#pragma unroll
            for (int pr = 0; pr < 4; pr++) {
                uint32_t rowb = (uint32_t)((wn * 64 + pr * 16) + b_ln) * 128
                              + kb + b_lkb;
                uint32_t offB = SW128(rowb);
                LDSM_X4(bH[pr], bh_base + offB);
                LDSM_X4(bL[pr], bl_base + offB);
            }
            // pass-major: 16 independent MMAs per pass -> no RAW chains
#pragma unroll
            for (int mi = 0; mi < 2; mi++)
#pragma unroll
                for (int ni = 0; ni < 8; ni++) {
                    int pr = ni >> 1, hf = (ni & 1) * 2;
                    MMA_BF16(acc[mi][ni], aH[mi], bH[pr][hf], bH[pr][hf + 1]);
                }
#pragma unroll
            for (int mi = 0; mi < 2; mi++)
#pragma unroll
                for (int ni = 0; ni < 8; ni++) {
                    int pr = ni >> 1, hf = (ni & 1) * 2;
                    MMA_BF16(acc[mi][ni], aH[mi], bL[pr][hf], bL[pr][hf + 1]);
                }
#pragma unroll
            for (int mi = 0; mi < 2; mi++)
#pragma unroll
                for (int ni = 0; ni < 8; ni++) {
                    int pr = ni >> 1, hf = (ni & 1) * 2;
                    MMA_BF16(acc[mi][ni], aL[mi], bH[pr][hf], bH[pr][hf + 1]);
                }
        }
        __syncthreads();
    }

    // ------------- epilogue (registers -> exp chain -> reduce) -------------
    float cc  = g_c;
    int gid  = l >> 2;
    int tid4 = l & 3;
    double tsum = 0.0;
#pragma unroll
    for (int mi = 0; mi < 2; mi++) {
        int r0 = wm * 32 + mi * 16 + gid;
        float sa0 = sqa_sm[r0];
        float sa1 = sqa_sm[r0 + 8];
#pragma unroll
        for (int ni = 0; ni < 8; ni++) {
            int c0 = wn * 64 + ni * 8 + 2 * tid4;
            float sb0 = sqb_sm[c0];
            float sb1 = sqb_sm[c0 + 1];
            float L2a = sa0 + sb0 - 2.f * acc[mi][ni][0];
            float L2b = sa0 + sb1 - 2.f * acc[mi][ni][1];
            float L2c = sa1 + sb0 - 2.f * acc[mi][ni][2];
            float L2d = sa1 + sb1 - 2.f * acc[mi][ni][3];
            float ua = __expf(-L2a * cc), ub = __expf(-L2b * cc);
            float uc = __expf(-L2c * cc), ud = __expf(-L2d * cc);
            float ua2 = ua * ua, ua4 = ua2 * ua2, ua8 = ua4 * ua4;
            float ub2 = ub * ub, ub4 = ub2 * ub2, ub8 = ub4 * ub4;
            float uc2 = uc * uc, uc4 = uc2 * uc2, uc8 = uc4 * uc4;
            float ud2 = ud * ud, ud4 = ud2 * ud2, ud8 = ud4 * ud4;
            float s1 = (ua + ua2 + ua4 + ua8 + ua8 * ua8)
                     + (ub + ub2 + ub4 + ub8 + ub8 * ub8);
            float s2 = (uc + uc2 + uc4 + uc8 + uc8 * uc8)
                     + (ud + ud2 + ud4 + ud8 + ud8 * ud8);
            tsum += (double)(s1 + s2);
        }
    }

    __syncthreads();
    double* red = (double*)(sm + OFF_STAGE0);
    red[t] = tsum;
    __syncthreads();
    for (int o = 128; o; o >>= 1) {
        if (t < o) red[t] += red[t + o];
        __syncthreads();
    }
    if (t == 0) {
        double w   = (bi == bj) ? 1.0 : 2.0;
        double sgn = ((bi < NBLK / 2) == (bj < NBLK / 2)) ? 1.0 : -1.0;
        g_partials[blockIdx.x] = w * sgn * red[0];
    }
}

// ---------------------------------------------------------------------------
// Pass 3: deterministic final reduction -> scalar mean.
// ---------------------------------------------------------------------------
__global__ void k_final(float* __restrict__ out) {
    __shared__ double red[256];
    int t = threadIdx.x;
    double s = 0.0;
    for (int i = t; i < NPAIRS; i += 256) s += g_partials[i];
    red[t] = s;
    __syncthreads();
    for (int o = 128; o; o >>= 1) {
        if (t < o) red[t] += red[t + o];
        __syncthreads();
    }
    if (t == 0) out[0] = (float)(red[0] / ((double)NSRC * (double)NSRC));
}

// ---------------------------------------------------------------------------
extern "C" void kernel_launch(void* const* d_in, const int* in_sizes, int n_in,
                              void* d_out, int out_size) {
    const float* src = (const float*)d_in[0];
    const float* tgt = (const float*)d_in[1];
    (void)in_sizes; (void)n_in; (void)out_size;

    cudaFuncSetAttribute(k_main, cudaFuncAttributeMaxDynamicSharedMemorySize, SMEM_SZ);

    k_convert<<<NBLK * 4, 256>>>(src, tgt);
    k_sq<<<NTOT / 8, 256>>>(src, tgt);
    k_col<<<NCOLB, 256>>>(src, tgt);
    k_colsum<<<D, 256>>>();
    k_bwf<<<1, 256>>>();
    k_main<<<NPAIRS, 256, SMEM_SZ>>>(src, tgt);
    k_final<<<1, 256>>>((float*)d_out);
}